// round 6
// baseline (speedup 1.0000x reference)
#include <cuda_runtime.h>
#include <math.h>

#define NP 8732
#define NG 20
#define NC 21
#define NB 128
#define TPB 256            // fused kernel block size
#define NT 35              // ceil(NP/TPB): 34 full tiles + one of 28
#define TPB2 512           // finalize kernel block size
#define PER 18             // ceil(NP/TPB2)
#define NWARP2 (TPB2/32)

__device__ float g_ce0[(size_t)NB * NP];            // lse - conf[...,0]
__device__ float g_iou[(size_t)NB * NP];            // per-prior best IoU
__device__ unsigned char g_bidx[(size_t)NB * NP];   // per-prior best GT idx
__device__ unsigned long long g_bestp[NB * NG];     // packed (iou_bits<<32)|~p
__device__ float g_pl[NB], g_pc[NB];
__device__ int g_pn[NB];
__device__ unsigned g_done;

__device__ __forceinline__ float warpSumF(float v) {
  #pragma unroll
  for (int o = 16; o > 0; o >>= 1) v += __shfl_down_sync(0xffffffffu, v, o);
  return v;
}
__device__ __forceinline__ int warpSumI(int v) {
  #pragma unroll
  for (int o = 16; o > 0; o >>= 1) v += __shfl_down_sync(0xffffffffu, v, o);
  return v;
}
__device__ __forceinline__ float sl1(float x) {
  float a = fabsf(x);
  return a < 1.f ? 0.5f * x * x : a - 0.5f;
}

// ============ Kernel 1 (fused): even blocks = lse, odd blocks = matching ====
// Even/odd interleave co-schedules HBM-bound (lse) and issue-bound (match)
// blocks on the same SMs so the two bottlenecks overlap.
union SmemF {
  float tile[TPB * NC];                       // 21504 B (lse path)
  struct { float4 g4[NG]; float ga[NG]; } m;  // matching path
};

__global__ void __launch_bounds__(TPB, 4)
fused_kernel(const float* __restrict__ conf, const float* __restrict__ dbox,
             const float* __restrict__ gtb)
{
  __shared__ SmemF s;
  const int id   = blockIdx.x;
  const int sub  = id >> 1;
  const int b    = sub / NT;
  const int t    = sub - b * NT;
  const int p0   = t * TPB;
  const int cnt  = min(TPB, NP - p0);
  const int tid  = threadIdx.x;

  if ((id & 1) == 0) {
    // ---------------- LSE path: ce0[b,p] = lse(conf[b,p,:]) - conf[b,p,0] ---
    const int nf4 = cnt * NC / 4;             // 256*21 and 28*21 both %4==0
    const float4* src = (const float4*)(conf + ((size_t)b * NP + p0) * NC);
    float4* dst = (float4*)s.tile;
    for (int i = tid; i < nf4; i += TPB) dst[i] = src[i];
    __syncthreads();
    if (tid < cnt) {
      const float* row = s.tile + tid * NC;   // stride 21: conflict-free
      float s0 = 0.f, s1 = 0.f, s2 = 0.f;
      #pragma unroll
      for (int k = 0; k < 21; k += 3) {
        s0 += __expf(row[k]);
        s1 += __expf(row[k + 1]);
        s2 += __expf(row[k + 2]);
      }
      g_ce0[(size_t)b * NP + p0 + tid] = __logf(s0 + s1 + s2) - row[0];
    }
  } else {
    // ---------------- Matching path: 1 prior/thread over 20 GT -------------
    if (tid < NG) {
      float4 g = ((const float4*)gtb)[b * NG + tid];
      s.m.g4[tid] = g;
      s.m.ga[tid] = (g.z - g.x) * (g.w - g.y);
    }
    __syncthreads();
    const int p = p0 + tid;
    const bool valid = tid < cnt;
    float ax0, ay0, ax1, ay1, areaA;
    if (valid) {
      float4 d = ((const float4*)dbox)[p];    // cx,cy,w,h
      float hx = 0.5f * d.z, hy = 0.5f * d.w;
      ax0 = d.x - hx; ay0 = d.y - hy; ax1 = d.x + hx; ay1 = d.y + hy;
      areaA = d.z * d.w;
    } else {
      ax0 = ay0 = 3.f; ax1 = ay1 = 3.f; areaA = 1.f;   // overlaps nothing
    }
    float best = 0.f; int bi = 0;             // all-zero row -> idx 0 (JAX)
    #pragma unroll
    for (int j = 0; j < NG; j++) {
      float4 g = s.m.g4[j];
      float w = fminf(ax1, g.z) - fmaxf(ax0, g.x);
      float h = fminf(ay1, g.w) - fmaxf(ay0, g.y);
      bool ov = (w > 0.f) && (h > 0.f);
      unsigned mm = __ballot_sync(0xffffffffu, ov);
      if (mm) {                               // warp-uniform branch
        float inter = ov ? w * h : 0.f;
        float iou = ov ? __fdividef(inter, areaA + s.m.ga[j] - inter) : 0.f;
        if (iou > best) { best = iou; bi = j; }   // strict >: FIRST max (axis=1)
        unsigned bits = __float_as_uint(iou);     // iou>=0: order-preserving
        unsigned mx = __reduce_max_sync(0xffffffffu, bits);
        unsigned em = __ballot_sync(0xffffffffu, bits == mx);
        int wl = __ffs(em) - 1;               // lowest lane = smallest p (ties)
        if ((tid & 31) == 0) {
          unsigned wp = (unsigned)(p0 + (tid & ~31) + wl);
          atomicMax(&g_bestp[b * NG + j],
                    ((unsigned long long)mx << 32) | (0xFFFFFFFFu - wp));
        }
      }
    }
    if (valid) {
      g_iou[(size_t)b * NP + p]  = best;
      g_bidx[(size_t)b * NP + p] = (unsigned char)bi;
    }
  }
}

// ============ Kernel 2: per-batch forced matches + losses + top-k ===========
struct SmemB {
  float iou[NP];
  float4 g4[NG];
  int glab[NG];
  int   redi[2][NWARP2];
  float redf[3][NWARP2];
  unsigned char bidx[NP];
};

__global__ void __launch_bounds__(TPB2, 1)
finalize_kernel(const float* __restrict__ loc, const float* __restrict__ conf,
                const float* __restrict__ dbox, const float* __restrict__ gtb,
                const int* __restrict__ gtl, float* __restrict__ out)
{
  __shared__ SmemB s;
  const int b   = blockIdx.x;
  const int tid = threadIdx.x;
  const int wi  = tid >> 5, li = tid & 31;

  // Load per-prior match results into smem (coalesced, L2-hot)
  {
    const float4* gi = (const float4*)(g_iou + (size_t)b * NP);
    float4* si = (float4*)s.iou;
    const unsigned* gb = (const unsigned*)(g_bidx + (size_t)b * NP);
    unsigned* sb = (unsigned*)s.bidx;
    for (int i = tid; i < NP / 4; i += TPB2) { si[i] = gi[i]; sb[i] = gb[i]; }
  }
  if (tid < NG) {
    s.g4[tid]   = ((const float4*)gtb)[b * NG + tid];
    s.glab[tid] = gtl[b * NG + tid];
  }
  __syncthreads();

  // Forced matches: sequential last-write-wins (matches JAX scatter order).
  // bp==0 (GT overlaps no prior) -> p=0, matching argmax-of-zeros semantics.
  if (tid == 0) {
    #pragma unroll
    for (int j = 0; j < NG; j++) {
      unsigned long long bp = g_bestp[b * NG + j];
      unsigned p = bp ? (0xFFFFFFFFu - (unsigned)(bp & 0xFFFFFFFFull)) : 0u;
      s.iou[p]  = 2.f;
      s.bidx[p] = (unsigned char)j;
    }
  }
  __syncthreads();

  // ---- losses; loss_c kept in registers ----
  float th_loc = 0.f, th_pce = 0.f; int th_np = 0;
  unsigned lcr[PER];
  #pragma unroll
  for (int i = 0; i < PER; i++) {
    int p = tid + i * TPB2;
    unsigned v = 0u;
    if (p < NP) {
      float biou = s.iou[p];
      int j = s.bidx[p];
      float ce0 = g_ce0[(size_t)b * NP + p];
      if (biou > 0.5f) {                      // pos (gt labels all >= 1)
        int lab = s.glab[j];
        const float* cp = conf + ((size_t)b * NP + p) * NC;
        float c0 = __ldg(cp), cl = __ldg(cp + lab);
        th_pce += ce0 + c0 - cl;              // ce = lse - conf[lab]
        th_np++;
        float4 d = ((const float4*)dbox)[p];
        float4 g = s.g4[j];
        float e0 = ((g.x + g.z) * 0.5f - d.x) / (0.1f * d.z);
        float e1 = ((g.y + g.w) * 0.5f - d.y) / (0.1f * d.w);
        float e2 = __logf((g.z - g.x) / d.z) * 5.f;
        float e3 = __logf((g.w - g.y) / d.w) * 5.f;
        float4 L = ((const float4*)loc)[(size_t)b * NP + p];
        th_loc += sl1(L.x - e0) + sl1(L.y - e1) + sl1(L.z - e2) + sl1(L.w - e3);
      } else {
        v = __float_as_uint(ce0);             // ce0 > 0: bits order-preserving
      }
    }
    lcr[i] = v;
  }

  {
    float a = warpSumF(th_loc), c = warpSumF(th_pce); int n = warpSumI(th_np);
    if (li == 0) { s.redf[0][wi] = a; s.redf[1][wi] = c; s.redi[0][wi] = n; }
  }
  __syncthreads();
  float locl = 0.f, pce = 0.f; int npos = 0;
  #pragma unroll
  for (int w = 0; w < NWARP2; w++) {
    locl += s.redf[0][w]; pce += s.redf[1][w]; npos += s.redi[0][w];
  }
  int k = min(3 * npos, NP - npos);

  // ---- top-k sum via binary search on float bit patterns ----
  // topk = sum_{v>t} v + (k - count_{v>t}) * t, t = k-th largest (bit pattern)
  float topk = 0.f;
  int par = 1;                                // double-buffered partials
  if (k > 0) {
    unsigned lo = 0u, hi = 0x7F800000u;
    while (lo < hi) {
      unsigned mid = (lo + hi) >> 1;
      int c = 0;
      #pragma unroll
      for (int i = 0; i < PER; i++) c += (lcr[i] > mid);
      c = warpSumI(c);
      if (li == 0) s.redi[par][wi] = c;
      __syncthreads();
      int tot = 0;
      #pragma unroll
      for (int w = 0; w < NWARP2; w++) tot += s.redi[par][w];
      if (tot < k) hi = mid; else lo = mid + 1u;   // uniform across block
      par ^= 1;
    }
    int m = 0; float sg = 0.f;
    #pragma unroll
    for (int i = 0; i < PER; i++) {
      unsigned u = lcr[i];
      if (u > lo) { m++; sg += __uint_as_float(u); }
    }
    m = warpSumI(m); sg = warpSumF(sg);
    if (li == 0) { s.redi[par][wi] = m; s.redf[2][wi] = sg; }
    __syncthreads();
    int mt = 0; float sgt = 0.f;
    #pragma unroll
    for (int w = 0; w < NWARP2; w++) { mt += s.redi[par][w]; sgt += s.redf[2][w]; }
    topk = sgt + (float)(k - mt) * __uint_as_float(lo);
  }

  if (tid == 0) {
    g_pl[b] = locl;
    g_pc[b] = pce + topk;
    g_pn[b] = npos;
    __threadfence();
    unsigned tk = atomicAdd(&g_done, 1u);     // modular ticket: replay-safe
    if ((tk % NB) == NB - 1) {                // last block finalizes
      __threadfence();
      volatile float* vl = g_pl;
      volatile float* vc = g_pc;
      volatile int*   vn = g_pn;
      float L = 0.f, C = 0.f; int n = 0;
      for (int i = 0; i < NB; i++) { L += vl[i]; C += vc[i]; n += vn[i]; }
      out[0] = (L + C) / (float)max(n, 1);
    }
  }
}

extern "C" void kernel_launch(void* const* d_in, const int* in_sizes, int n_in,
                              void* d_out, int out_size) {
  const float* loc  = (const float*)d_in[0];
  const float* conf = (const float*)d_in[1];
  const float* dbox = (const float*)d_in[2];
  const float* gtb  = (const float*)d_in[3];
  const int*   gtl  = (const int*)d_in[4];
  float* out = (float*)d_out;

  fused_kernel<<<2 * NT * NB, TPB>>>(conf, dbox, gtb);
  finalize_kernel<<<NB, TPB2>>>(loc, conf, dbox, gtb, gtl, out);
}